// round 5
// baseline (speedup 1.0000x reference)
#include <cuda_runtime.h>
#include <cstdint>

#define BNUM 2
#define SLEN 2048
#define DDIM 1024
#define HNUM 16
#define DKQ  64
#define PAD  68

// Scratch (all __device__, allocation-rule compliant):
__device__ float    g_a[3][BNUM*SLEN*DDIM];          // tf32-rounded inputs
__device__ float    g_wt[3][DDIM*DDIM];              // transposed + tf32 weights
__device__ uint32_t g_qhi[BNUM*HNUM*SLEN*DKQ];       // Q*0.125 split hi [bh][s][dk]
__device__ uint32_t g_qlo[BNUM*HNUM*SLEN*DKQ];
__device__ uint32_t g_khi[BNUM*HNUM*SLEN*DKQ];       // K split hi [bh][s][dk]
__device__ uint32_t g_klo[BNUM*HNUM*SLEN*DKQ];
__device__ uint32_t g_vt [BNUM*HNUM*SLEN*DKQ];       // V tf32 transposed [bh][dk][s]

// ---------------- helpers ----------------
__device__ __forceinline__ uint32_t f2tf32(float x) {
    uint32_t y;
    asm("cvt.rna.tf32.f32 %0, %1;" : "=r"(y) : "f"(x));
    return y;
}
__device__ __forceinline__ uint32_t smem_u32(const void* p) {
    uint32_t a;
    asm("{ .reg .u64 t; cvta.to.shared.u64 t, %1; cvt.u32.u64 %0, t; }"
        : "=r"(a) : "l"(p));
    return a;
}
__device__ __forceinline__ void cp16(uint32_t dst, const void* src) {
    asm volatile("cp.async.cg.shared.global [%0], [%1], 16;"
                 :: "r"(dst), "l"(src));
}
#define CP_COMMIT() asm volatile("cp.async.commit_group;" ::: "memory")
#define CP_WAIT1()  asm volatile("cp.async.wait_group 1;" ::: "memory")
#define CP_WAIT0()  asm volatile("cp.async.wait_group 0;" ::: "memory")

__device__ __forceinline__ void mma_tf32(
    float& d0, float& d1, float& d2, float& d3,
    uint32_t a0, uint32_t a1, uint32_t a2, uint32_t a3,
    uint32_t b0, uint32_t b1)
{
    asm volatile(
        "mma.sync.aligned.m16n8k8.row.col.f32.tf32.tf32.f32 "
        "{%0,%1,%2,%3}, {%4,%5,%6,%7}, {%8,%9}, {%0,%1,%2,%3};"
        : "+f"(d0), "+f"(d1), "+f"(d2), "+f"(d3)
        : "r"(a0), "r"(a1), "r"(a2), "r"(a3), "r"(b0), "r"(b1));
}

// ---------------- input tf32 rounding pre-pass ----------------
__global__ __launch_bounds__(256) void cvt_kernel(
    const float4* __restrict__ in, float4* __restrict__ out, int n4)
{
    int i = blockIdx.x * blockDim.x + threadIdx.x;
    if (i < n4) {
        float4 v = in[i];
        float4 o;
        o.x = __uint_as_float(f2tf32(v.x));
        o.y = __uint_as_float(f2tf32(v.y));
        o.z = __uint_as_float(f2tf32(v.z));
        o.w = __uint_as_float(f2tf32(v.w));
        out[i] = o;
    }
}

// ---------------- weight transpose + tf32: Wt[n][k] = tf32(W[k][n]) ----------------
__global__ __launch_bounds__(256) void transpose_kernel(
    const float* __restrict__ in, float* __restrict__ out)
{
    __shared__ float t[32][33];
    int x = blockIdx.x*32 + threadIdx.x;
    int y0 = blockIdx.y*32 + threadIdx.y;
#pragma unroll
    for (int j = 0; j < 32; j += 8)
        t[threadIdx.y + j][threadIdx.x] = in[(size_t)(y0 + j)*DDIM + x];
    __syncthreads();
    int xo = blockIdx.y*32 + threadIdx.x;
    int yo = blockIdx.x*32 + threadIdx.y;
#pragma unroll
    for (int j = 0; j < 32; j += 8)
        out[(size_t)(yo + j)*DDIM + xo] =
            __uint_as_float(f2tf32(t[threadIdx.x][threadIdx.y + j]));
}

// ---------------- cp.async double-buffered tf32 HMMA projection ----------------
// C[4096,1024] = A @ Wt^T + bias. Tile 128x128, K-chunk 32, 2-stage pipeline.
// MODE 0: Q -> scale 0.125, split hi/lo, [bh][s][dk]
// MODE 1: K -> split hi/lo, [bh][s][dk]
// MODE 2: V -> tf32, transposed [bh][dk][s]
template<int MODE>
__global__ __launch_bounds__(256, 2) void proj_mma_kernel(
    const float* __restrict__ A, const float* __restrict__ Wt,
    const float* __restrict__ bias,
    uint32_t* __restrict__ out_hi, uint32_t* __restrict__ out_lo)
{
    extern __shared__ uint32_t psm[];        // As[2][128][36] | Bs[2][128][36]
    uint32_t* As = psm;
    uint32_t* Bs = psm + 2*128*36;
    const uint32_t as_u = smem_u32(As);
    const uint32_t bs_u = smem_u32(Bs);

    const int tid  = threadIdx.x;
    const int wid  = tid >> 5;
    const int lane = tid & 31;
    const int lr   = lane >> 2;
    const int lc   = lane & 3;
    const int wm   = (wid >> 2) * 64;
    const int wn   = (wid & 3) * 32;
    const int col0 = blockIdx.x << 7;
    const int row0 = blockIdx.y << 7;

    const float* Abase = A  + (size_t)row0 * DDIM;
    const float* Bbase = Wt + (size_t)col0 * DDIM;

    auto issue = [&](int c, int s) {
#pragma unroll
        for (int it = 0; it < 4; it++) {
            int f = tid + it * 256;          // 0..1023
            int r = f >> 3;
            int o = (f & 7) * 16;            // byte offset within 128B row
            uint32_t d = (uint32_t)((s*128 + r) * 144) + o;
            cp16(as_u + d, (const char*)(Abase + (size_t)r * DDIM + c*32) + o);
            cp16(bs_u + d, (const char*)(Bbase + (size_t)r * DDIM + c*32) + o);
        }
    };

    float acc[4][4][4];
#pragma unroll
    for (int mt = 0; mt < 4; mt++)
#pragma unroll
        for (int nt = 0; nt < 4; nt++)
#pragma unroll
            for (int i = 0; i < 4; i++) acc[mt][nt][i] = 0.f;

    issue(0, 0); CP_COMMIT();

    for (int c = 0; c < 32; c++) {
        const int s = c & 1;
        __syncthreads();                      // prior readers of stage s^1 done
        if (c < 31) { issue(c + 1, s ^ 1); CP_COMMIT(); CP_WAIT1(); }
        else        { CP_WAIT0(); }
        __syncthreads();                      // stage s visible to all

        const uint32_t* Ast = As + s*128*36;
        const uint32_t* Bst = Bs + s*128*36;
#pragma unroll
        for (int ks = 0; ks < 4; ks++) {
            const int k8 = ks * 8;
            uint32_t a[4][4];
#pragma unroll
            for (int mt = 0; mt < 4; mt++) {
                int r = wm + mt * 16 + lr;
                a[mt][0] = Ast[r*36 + k8 + lc];
                a[mt][1] = Ast[(r+8)*36 + k8 + lc];
                a[mt][2] = Ast[r*36 + k8 + lc + 4];
                a[mt][3] = Ast[(r+8)*36 + k8 + lc + 4];
            }
#pragma unroll
            for (int nt = 0; nt < 4; nt++) {
                int n = wn + nt * 8 + lr;
                uint32_t b0 = Bst[n*36 + k8 + lc];
                uint32_t b1 = Bst[n*36 + k8 + lc + 4];
#pragma unroll
                for (int mt = 0; mt < 4; mt++)
                    mma_tf32(acc[mt][nt][0], acc[mt][nt][1],
                             acc[mt][nt][2], acc[mt][nt][3],
                             a[mt][0], a[mt][1], a[mt][2], a[mt][3], b0, b1);
            }
        }
    }

    // Epilogue
#pragma unroll
    for (int mt = 0; mt < 4; mt++) {
#pragma unroll
        for (int nt = 0; nt < 4; nt++) {
            int col = col0 + wn + nt * 8 + 2 * lc;
            float2 bb = *(const float2*)(bias + col);
            int head = col >> 6;
            int dk   = col & 63;
#pragma unroll
            for (int h = 0; h < 2; h++) {
                int row = row0 + wm + mt * 16 + lr + h * 8;
                int bi  = row >> 11;
                int si  = row & (SLEN - 1);
                float vx = acc[mt][nt][2*h + 0] + bb.x;
                float vy = acc[mt][nt][2*h + 1] + bb.y;
                if (MODE == 0) { vx *= 0.125f; vy *= 0.125f; }
                if (MODE == 2) {
                    size_t base = ((size_t)(bi * HNUM + head) * DKQ + dk) * SLEN + si;
                    out_hi[base]        = f2tf32(vx);
                    out_hi[base + SLEN] = f2tf32(vy);
                } else {
                    uint32_t hx = f2tf32(vx);
                    uint32_t hy = f2tf32(vy);
                    uint32_t lx = f2tf32(vx - __uint_as_float(hx));
                    uint32_t ly = f2tf32(vy - __uint_as_float(hy));
                    size_t idx = ((size_t)(bi * HNUM + head) * SLEN + si) * DKQ + dk;
                    uint2 hv = { hx, hy }, lv = { lx, ly };
                    *(uint2*)(out_hi + idx) = hv;
                    *(uint2*)(out_lo + idx) = lv;
                }
            }
        }
    }
}

// ---------------- cp.async pipelined tensor-core flash attention ----------------
// One CTA = (bh, 64-query tile), 4 warps, warp = 16 q-rows.
// QK^T: tf32x3 (pre-split Q/K). PV: tf32 (pre-transposed V). 2-stage K/V pipeline.
#define T64 (64*PAD)
__global__ __launch_bounds__(128) void attn_mma_kernel(
    const uint32_t* __restrict__ Qhi_g, const uint32_t* __restrict__ Qlo_g,
    const uint32_t* __restrict__ Khi_g, const uint32_t* __restrict__ Klo_g,
    const uint32_t* __restrict__ Vt_g,  float* __restrict__ out)
{
    extern __shared__ uint32_t sm[];
    // layout: Qhi | Qlo | {Khi,Klo,Vt} x2 stages | Ps
    uint32_t* Qhi = sm;
    uint32_t* Qlo = sm + T64;
    uint32_t* Ps  = sm + 8*T64;
    const uint32_t sm_u = smem_u32(sm);

    const int tid  = threadIdx.x;
    const int w    = tid >> 5;
    const int lane = tid & 31;
    const int lr   = lane >> 2;
    const int lc   = lane & 3;
    const int bh   = blockIdx.x;
    const int qt   = (gridDim.y - 1) - blockIdx.y;

    const uint32_t* Qh_src = Qhi_g + ((size_t)bh * SLEN + (size_t)qt * 64) * DKQ;
    const uint32_t* Ql_src = Qlo_g + ((size_t)bh * SLEN + (size_t)qt * 64) * DKQ;

    auto issue_kv = [&](int kt, int s) {
        const uint32_t* Kh = Khi_g + ((size_t)bh * SLEN + (size_t)kt * 64) * DKQ;
        const uint32_t* Kl = Klo_g + ((size_t)bh * SLEN + (size_t)kt * 64) * DKQ;
        const uint32_t* Vt = Vt_g  + (size_t)bh * DKQ * SLEN + (size_t)kt * 64;
        const uint32_t kb = sm_u + (uint32_t)(2 + 3*s) * T64 * 4;
#pragma unroll
        for (int it = 0; it < 8; it++) {
            int f = tid + it * 128;          // 0..1023
            int r = f >> 4;
            int o = (f & 15) * 16;
            uint32_t d = (uint32_t)(r * PAD * 4) + o;
            cp16(kb + d,             (const char*)(Kh + (size_t)r * DKQ) + o);
            cp16(kb + T64*4 + d,     (const char*)(Kl + (size_t)r * DKQ) + o);
            cp16(kb + 2*T64*4 + d,   (const char*)(Vt + (size_t)r * SLEN) + o);
        }
    };

    // prologue: Q (both halves) + stage0 K/V in one commit group
#pragma unroll
    for (int it = 0; it < 8; it++) {
        int f = tid + it * 128;
        int r = f >> 4;
        int o = (f & 15) * 16;
        uint32_t d = (uint32_t)(r * PAD * 4) + o;
        cp16(sm_u + d,           (const char*)(Qh_src + (size_t)r * DKQ) + o);
        cp16(sm_u + T64*4 + d,   (const char*)(Ql_src + (size_t)r * DKQ) + o);
    }
    issue_kv(0, 0);
    CP_COMMIT();

    float accO[8][4];
#pragma unroll
    for (int nf = 0; nf < 8; nf++)
#pragma unroll
        for (int i = 0; i < 4; i++) accO[nf][i] = 0.f;
    float mrow[2] = { -1e30f, -1e30f };
    float lrow[2] = { 0.f, 0.f };

    const int qrow0 = qt*64 + w*16 + lr;
    const int qbase = (w*16 + lr) * PAD;

    for (int kt = 0; kt <= qt; kt++) {
        const int s = kt & 1;
        __syncthreads();                      // stage s^1 readers (kt-1) done
        if (kt < qt) { issue_kv(kt + 1, s ^ 1); CP_COMMIT(); CP_WAIT1(); }
        else         { CP_WAIT0(); }
        __syncthreads();                      // stage s (+ Q on kt=0) visible

        const uint32_t* Khs = sm + (2 + 3*s) * T64;
        const uint32_t* Kls = Khs + T64;
        const uint32_t* Vts = Khs + 2*T64;

        // ---- scores: tf32x3 QK^T ----
        float accS[8][4];
#pragma unroll
        for (int nf = 0; nf < 8; nf++)
#pragma unroll
            for (int i = 0; i < 4; i++) accS[nf][i] = 0.f;

#pragma unroll
        for (int ks = 0; ks < 8; ks++) {
            const int k8 = ks * 8;
            uint32_t ah0 = Qhi[qbase + k8 + lc];
            uint32_t ah2 = Qhi[qbase + k8 + lc + 4];
            uint32_t ah1 = Qhi[qbase + 8*PAD + k8 + lc];
            uint32_t ah3 = Qhi[qbase + 8*PAD + k8 + lc + 4];
            uint32_t al0 = Qlo[qbase + k8 + lc];
            uint32_t al2 = Qlo[qbase + k8 + lc + 4];
            uint32_t al1 = Qlo[qbase + 8*PAD + k8 + lc];
            uint32_t al3 = Qlo[qbase + 8*PAD + k8 + lc + 4];
#pragma unroll
            for (int nf = 0; nf < 8; nf++) {
                int nb = (nf*8 + lr) * PAD + k8 + lc;
                uint32_t bh0 = Khs[nb], bh1 = Khs[nb + 4];
                uint32_t bl0 = Kls[nb], bl1 = Kls[nb + 4];
                mma_tf32(accS[nf][0], accS[nf][1], accS[nf][2], accS[nf][3],
                         ah0, ah1, ah2, ah3, bh0, bh1);
                mma_tf32(accS[nf][0], accS[nf][1], accS[nf][2], accS[nf][3],
                         ah0, ah1, ah2, ah3, bl0, bl1);
                mma_tf32(accS[nf][0], accS[nf][1], accS[nf][2], accS[nf][3],
                         al0, al1, al2, al3, bh0, bh1);
            }
        }

        if (kt == qt) {
#pragma unroll
            for (int nf = 0; nf < 8; nf++) {
                int gc = kt*64 + nf*8 + 2*lc;
                if (gc     > qrow0)     accS[nf][0] = -1e30f;
                if (gc + 1 > qrow0)     accS[nf][1] = -1e30f;
                if (gc     > qrow0 + 8) accS[nf][2] = -1e30f;
                if (gc + 1 > qrow0 + 8) accS[nf][3] = -1e30f;
            }
        }

        // ---- online softmax ----
#pragma unroll
        for (int h = 0; h < 2; h++) {
            const int i0 = 2*h, i1 = 2*h + 1;
            float rmax = accS[0][i0];
#pragma unroll
            for (int nf = 0; nf < 8; nf++) {
                rmax = fmaxf(rmax, accS[nf][i0]);
                rmax = fmaxf(rmax, accS[nf][i1]);
            }
            rmax = fmaxf(rmax, __shfl_xor_sync(0xffffffffu, rmax, 1));
            rmax = fmaxf(rmax, __shfl_xor_sync(0xffffffffu, rmax, 2));
            float mn   = fmaxf(mrow[h], rmax);
            float corr = __expf(mrow[h] - mn);
            mrow[h] = mn;
            float rsum = 0.f;
            const int pb = qbase + h*8*PAD;
#pragma unroll
            for (int nf = 0; nf < 8; nf++) {
                uint32_t u0 = f2tf32(__expf(accS[nf][i0] - mn));
                uint32_t u1 = f2tf32(__expf(accS[nf][i1] - mn));
                rsum += __uint_as_float(u0) + __uint_as_float(u1);
                uint2 pp = { u0, u1 };
                *(uint2*)&Ps[pb + nf*8 + 2*lc] = pp;
                accO[nf][i0] *= corr;
                accO[nf][i1] *= corr;
            }
            rsum += __shfl_xor_sync(0xffffffffu, rsum, 1);
            rsum += __shfl_xor_sync(0xffffffffu, rsum, 2);
            lrow[h] = lrow[h] * corr + rsum;
        }
        __syncwarp();

        // ---- accO += P @ V ----
#pragma unroll
        for (int ks = 0; ks < 8; ks++) {
            const int k8 = ks * 8;
            uint32_t a0 = Ps[qbase + k8 + lc];
            uint32_t a2 = Ps[qbase + k8 + lc + 4];
            uint32_t a1 = Ps[qbase + 8*PAD + k8 + lc];
            uint32_t a3 = Ps[qbase + 8*PAD + k8 + lc + 4];
#pragma unroll
            for (int nf = 0; nf < 8; nf++) {
                int nb = (nf*8 + lr) * PAD + k8 + lc;
                uint32_t b0 = Vts[nb], b1 = Vts[nb + 4];
                mma_tf32(accO[nf][0], accO[nf][1], accO[nf][2], accO[nf][3],
                         a0, a1, a2, a3, b0, b1);
            }
        }
    }

    // ---- epilogue ----
    const int b = bh >> 4, h = bh & 15;
    const float inv0 = 1.f / lrow[0];
    const float inv1 = 1.f / lrow[1];
    const int s0 = qt*64 + w*16 + lr;
    const int s1 = s0 + 8;
#pragma unroll
    for (int nf = 0; nf < 8; nf++) {
        int col = h*DKQ + nf*8 + 2*lc;
        float2 v0 = { accO[nf][0] * inv0, accO[nf][1] * inv0 };
        float2 v1 = { accO[nf][2] * inv1, accO[nf][3] * inv1 };
        *(float2*)(out + ((size_t)b * SLEN + s0) * DDIM + col) = v0;
        *(float2*)(out + ((size_t)b * SLEN + s1) * DDIM + col) = v1;
    }
}

extern "C" void kernel_launch(void* const* d_in, const int* in_sizes, int n_in,
                              void* d_out, int out_size) {
    const float* q  = (const float*)d_in[0];
    const float* k  = (const float*)d_in[1];
    const float* v  = (const float*)d_in[2];
    const float* Wq = (const float*)d_in[3];
    const float* bq = (const float*)d_in[4];
    const float* Wk = (const float*)d_in[5];
    const float* bk = (const float*)d_in[6];
    const float* Wv = (const float*)d_in[7];
    const float* bv = (const float*)d_in[8];
    float* out = (float*)d_out;

    float *ga, *gwt;
    uint32_t *gqh, *gql, *gkh, *gkl, *gvt;
    cudaGetSymbolAddress((void**)&ga,  g_a);
    cudaGetSymbolAddress((void**)&gwt, g_wt);
    cudaGetSymbolAddress((void**)&gqh, g_qhi);
    cudaGetSymbolAddress((void**)&gql, g_qlo);
    cudaGetSymbolAddress((void**)&gkh, g_khi);
    cudaGetSymbolAddress((void**)&gkl, g_klo);
    cudaGetSymbolAddress((void**)&gvt, g_vt);

    const size_t NA = (size_t)BNUM*SLEN*DDIM;
    const int n4 = (int)(NA / 4);
    cvt_kernel<<<(n4 + 255)/256, 256>>>((const float4*)q, (float4*)(ga + 0*NA), n4);
    cvt_kernel<<<(n4 + 255)/256, 256>>>((const float4*)k, (float4*)(ga + 1*NA), n4);
    cvt_kernel<<<(n4 + 255)/256, 256>>>((const float4*)v, (float4*)(ga + 2*NA), n4);

    dim3 tgrid(DDIM/32, DDIM/32), tblk(32, 8);
    transpose_kernel<<<tgrid, tblk>>>(Wq, gwt + 0*DDIM*DDIM);
    transpose_kernel<<<tgrid, tblk>>>(Wk, gwt + 1*DDIM*DDIM);
    transpose_kernel<<<tgrid, tblk>>>(Wv, gwt + 2*DDIM*DDIM);

    const int proj_smem = 2 * 2 * 128 * 36 * 4;   // 73728
    cudaFuncSetAttribute(proj_mma_kernel<0>,
        cudaFuncAttributeMaxDynamicSharedMemorySize, proj_smem);
    cudaFuncSetAttribute(proj_mma_kernel<1>,
        cudaFuncAttributeMaxDynamicSharedMemorySize, proj_smem);
    cudaFuncSetAttribute(proj_mma_kernel<2>,
        cudaFuncAttributeMaxDynamicSharedMemorySize, proj_smem);

    dim3 pgrid(DDIM/128, (BNUM*SLEN)/128);
    proj_mma_kernel<0><<<pgrid, 256, proj_smem>>>(ga + 0*NA, gwt + 0*DDIM*DDIM, bq, gqh, gql);
    proj_mma_kernel<1><<<pgrid, 256, proj_smem>>>(ga + 1*NA, gwt + 1*DDIM*DDIM, bk, gkh, gkl);
    proj_mma_kernel<2><<<pgrid, 256, proj_smem>>>(ga + 2*NA, gwt + 2*DDIM*DDIM, bv, gvt, nullptr);

    const int attn_smem = 9 * T64 * 4;            // 156672
    cudaFuncSetAttribute(attn_mma_kernel,
        cudaFuncAttributeMaxDynamicSharedMemorySize, attn_smem);
    attn_mma_kernel<<<dim3(BNUM*HNUM, SLEN/64), 128, attn_smem>>>(
        gqh, gql, gkh, gkl, gvt, out);
}

// round 6
// speedup vs baseline: 1.5195x; 1.5195x over previous
#include <cuda_runtime.h>
#include <cuda_bf16.h>
#include <cstdint>

#define BNUM 2
#define SLEN 2048
#define DDIM 1024
#define HNUM 16
#define DKQ  64
#define PAD  68
#define WPD  36   // word pitch for packed bf16x2 rows (32 words + pad)

// Scratch: projected Q/K/V in [B, H, S, DK] fp32 + transposed weights [N, K].
__device__ float g_q[BNUM*HNUM*SLEN*DKQ];
__device__ float g_k[BNUM*HNUM*SLEN*DKQ];
__device__ float g_v[BNUM*HNUM*SLEN*DKQ];
__device__ float g_wt[3][DDIM*DDIM];

// ---------------- helpers ----------------
__device__ __forceinline__ uint32_t f2tf32(float x) {
    uint32_t y;
    asm("cvt.rna.tf32.f32 %0, %1;" : "=r"(y) : "f"(x));
    return y;
}
__device__ __forceinline__ void mma_tf32(
    float& d0, float& d1, float& d2, float& d3,
    uint32_t a0, uint32_t a1, uint32_t a2, uint32_t a3,
    uint32_t b0, uint32_t b1)
{
    asm volatile(
        "mma.sync.aligned.m16n8k8.row.col.f32.tf32.tf32.f32 "
        "{%0,%1,%2,%3}, {%4,%5,%6,%7}, {%8,%9}, {%0,%1,%2,%3};"
        : "+f"(d0), "+f"(d1), "+f"(d2), "+f"(d3)
        : "r"(a0), "r"(a1), "r"(a2), "r"(a3), "r"(b0), "r"(b1));
}
__device__ __forceinline__ void mma_bf16(
    float& d0, float& d1, float& d2, float& d3,
    uint32_t a0, uint32_t a1, uint32_t a2, uint32_t a3,
    uint32_t b0, uint32_t b1)
{
    asm volatile(
        "mma.sync.aligned.m16n8k16.row.col.f32.bf16.bf16.f32 "
        "{%0,%1,%2,%3}, {%4,%5,%6,%7}, {%8,%9}, {%0,%1,%2,%3};"
        : "+f"(d0), "+f"(d1), "+f"(d2), "+f"(d3)
        : "r"(a0), "r"(a1), "r"(a2), "r"(a3), "r"(b0), "r"(b1));
}
// Split (x0,x1) into bf16 hi/lo pairs, packed (x0 in low half).
__device__ __forceinline__ void split_pack_bf16(
    float x0, float x1, uint32_t& whi, uint32_t& wlo)
{
    __nv_bfloat16 h0 = __float2bfloat16(x0);
    __nv_bfloat16 h1 = __float2bfloat16(x1);
    float r0 = x0 - __bfloat162float(h0);
    float r1 = x1 - __bfloat162float(h1);
    __nv_bfloat16 l0 = __float2bfloat16(r0);
    __nv_bfloat16 l1 = __float2bfloat16(r1);
    whi = (uint32_t)__bfloat16_as_ushort(h0) |
          ((uint32_t)__bfloat16_as_ushort(h1) << 16);
    wlo = (uint32_t)__bfloat16_as_ushort(l0) |
          ((uint32_t)__bfloat16_as_ushort(l1) << 16);
}

// ---------------- weight transpose: Wt[n][k] = W[k][n] ----------------
__global__ __launch_bounds__(256) void transpose_kernel(
    const float* __restrict__ in, float* __restrict__ out)
{
    __shared__ float t[32][33];
    int x = blockIdx.x*32 + threadIdx.x;
    int y0 = blockIdx.y*32 + threadIdx.y;
#pragma unroll
    for (int j = 0; j < 32; j += 8)
        t[threadIdx.y + j][threadIdx.x] = in[(size_t)(y0 + j)*DDIM + x];
    __syncthreads();
    int xo = blockIdx.y*32 + threadIdx.x;
    int yo = blockIdx.x*32 + threadIdx.y;
#pragma unroll
    for (int j = 0; j < 32; j += 8)
        out[(size_t)(yo + j)*DDIM + xo] = t[threadIdx.x][threadIdx.y + j];
}

// ---------------- tf32 HMMA projection GEMM, 3 GEMMs merged on z ----------------
__global__ __launch_bounds__(256, 2) void proj_mma_kernel(
    const float* __restrict__ A0, const float* __restrict__ A1, const float* __restrict__ A2,
    const float* __restrict__ W0, const float* __restrict__ W1, const float* __restrict__ W2,
    const float* __restrict__ bias0, const float* __restrict__ bias1, const float* __restrict__ bias2,
    float* __restrict__ o0, float* __restrict__ o1, float* __restrict__ o2)
{
    __shared__ uint32_t As[128][36];
    __shared__ uint32_t Bs[128][36];

    const int z = blockIdx.z;
    const float* A    = (z == 0) ? A0 : (z == 1) ? A1 : A2;
    const float* Wt   = (z == 0) ? W0 : (z == 1) ? W1 : W2;
    const float* bias = (z == 0) ? bias0 : (z == 1) ? bias1 : bias2;
    float*       out  = (z == 0) ? o0 : (z == 1) ? o1 : o2;

    const int tid  = threadIdx.x;
    const int wid  = tid >> 5;
    const int lane = tid & 31;
    const int lr   = lane >> 2;
    const int lc   = lane & 3;
    const int wm   = (wid >> 2) * 64;
    const int wn   = (wid & 3) * 32;
    const int col0 = blockIdx.x << 7;
    const int row0 = blockIdx.y << 7;

    float acc[4][4][4];
#pragma unroll
    for (int mt = 0; mt < 4; mt++)
#pragma unroll
        for (int nt = 0; nt < 4; nt++)
#pragma unroll
            for (int i = 0; i < 4; i++) acc[mt][nt][i] = 0.f;

    for (int kc = 0; kc < DDIM; kc += 32) {
        __syncthreads();
#pragma unroll
        for (int it = 0; it < 4; it++) {
            int f  = tid + it * 256;
            int r  = f >> 3;
            int c4 = (f & 7) << 2;
            float4 va = *(const float4*)(A  + (size_t)(row0 + r) * DDIM + kc + c4);
            float4 vb = *(const float4*)(Wt + (size_t)(col0 + r) * DDIM + kc + c4);
            uint4 ua = { f2tf32(va.x), f2tf32(va.y), f2tf32(va.z), f2tf32(va.w) };
            uint4 ub = { f2tf32(vb.x), f2tf32(vb.y), f2tf32(vb.z), f2tf32(vb.w) };
            *(uint4*)&As[r][c4] = ua;
            *(uint4*)&Bs[r][c4] = ub;
        }
        __syncthreads();

#pragma unroll
        for (int ks = 0; ks < 4; ks++) {
            const int k8 = ks * 8;
            uint32_t a[4][4];
#pragma unroll
            for (int mt = 0; mt < 4; mt++) {
                int r = wm + mt * 16 + lr;
                a[mt][0] = As[r    ][k8 + lc];
                a[mt][1] = As[r + 8][k8 + lc];
                a[mt][2] = As[r    ][k8 + lc + 4];
                a[mt][3] = As[r + 8][k8 + lc + 4];
            }
#pragma unroll
            for (int nt = 0; nt < 4; nt++) {
                int n = wn + nt * 8 + lr;
                uint32_t b0 = Bs[n][k8 + lc];
                uint32_t b1 = Bs[n][k8 + lc + 4];
#pragma unroll
                for (int mt = 0; mt < 4; mt++)
                    mma_tf32(acc[mt][nt][0], acc[mt][nt][1],
                             acc[mt][nt][2], acc[mt][nt][3],
                             a[mt][0], a[mt][1], a[mt][2], a[mt][3], b0, b1);
            }
        }
    }

#pragma unroll
    for (int mt = 0; mt < 4; mt++) {
#pragma unroll
        for (int nt = 0; nt < 4; nt++) {
            int row = row0 + wm + mt * 16 + lr;
            int col = col0 + wn + nt * 8 + 2 * lc;
            float2 bb = *(const float2*)(bias + col);
            int head = col >> 6;
            int dk   = col & 63;
            int b0i  = row >> 11;
            int s0   = row & (SLEN - 1);
            float2 v0 = { acc[mt][nt][0] + bb.x, acc[mt][nt][1] + bb.y };
            *(float2*)(out + ((size_t)(b0i * HNUM + head) * SLEN + s0) * DKQ + dk) = v0;
            int row2 = row + 8;
            int b1i  = row2 >> 11;
            int s1   = row2 & (SLEN - 1);
            float2 v1 = { acc[mt][nt][2] + bb.x, acc[mt][nt][3] + bb.y };
            *(float2*)(out + ((size_t)(b1i * HNUM + head) * SLEN + s1) * DKQ + dk) = v1;
        }
    }
}

// ---------------- tensor-core flash attention ----------------
// One CTA = (bh, 64-query tile), 4 warps, warp = 16 q-rows.
// QK^T: bf16x2 via m16n8k16 (hi*hi + hi*lo + lo*hi). PV: plain tf32 m16n8k8.
__global__ __launch_bounds__(128) void attn_mma_kernel(
    const float* __restrict__ Q, const float* __restrict__ K,
    const float* __restrict__ V, float* __restrict__ out)
{
    extern __shared__ uint32_t sm[];
    uint32_t* Qh = sm;                         // [64][WPD] packed bf16x2 (2 d / word)
    uint32_t* Ql = sm + 64*WPD;
    uint32_t* Kh = sm + 2*64*WPD;              // [64][WPD]
    uint32_t* Kl = sm + 3*64*WPD;
    uint32_t* Vt = sm + 4*64*WPD;              // [64][PAD] tf32, d-major
    uint32_t* Ps = sm + 4*64*WPD + 64*PAD;     // [64][PAD] tf32

    const int tid  = threadIdx.x;
    const int w    = tid >> 5;
    const int lane = tid & 31;
    const int lr   = lane >> 2;
    const int lc   = lane & 3;
    const int bh   = blockIdx.x;
    const int qt   = (gridDim.y - 1) - blockIdx.y;  // big tiles first

    // Load Q tile, pre-scaled by 1/sqrt(dk)=0.125, split+pack bf16x2.
    const float* Qb = Q + ((size_t)bh * SLEN + (size_t)qt * 64) * DKQ;
#pragma unroll
    for (int it = 0; it < 8; it++) {
        int f = tid + it * 128;
        int r = f >> 4, c = (f & 15) << 2;
        float4 v4 = *(const float4*)(Qb + r * DKQ + c);
        v4.x *= 0.125f; v4.y *= 0.125f; v4.z *= 0.125f; v4.w *= 0.125f;
        uint2 hw, lw;
        split_pack_bf16(v4.x, v4.y, hw.x, lw.x);
        split_pack_bf16(v4.z, v4.w, hw.y, lw.y);
        *(uint2*)&Qh[r*WPD + (c >> 1)] = hw;
        *(uint2*)&Ql[r*WPD + (c >> 1)] = lw;
    }

    float accO[8][4];
#pragma unroll
    for (int nf = 0; nf < 8; nf++)
#pragma unroll
        for (int i = 0; i < 4; i++) accO[nf][i] = 0.f;
    float mrow[2] = { -1e30f, -1e30f };
    float lrow[2] = { 0.f, 0.f };

    const int qrow0 = qt*64 + w*16 + lr;
    const int qbw   = (w*16 + lr) * WPD;   // packed-row base (Q)
    const int qbp   = (w*16 + lr) * PAD;   // tf32-row base (Ps)

    for (int kt = 0; kt <= qt; kt++) {
        __syncthreads();   // previous iteration's K/V/P consumers are done
        const float* Kb = K + ((size_t)bh * SLEN + (size_t)kt * 64) * DKQ;
        const float* Vb = V + ((size_t)bh * SLEN + (size_t)kt * 64) * DKQ;
#pragma unroll
        for (int it = 0; it < 8; it++) {
            int f = tid + it * 128;
            int r = f >> 4, c = (f & 15) << 2;
            float4 k4 = *(const float4*)(Kb + r * DKQ + c);
            uint2 hw, lw;
            split_pack_bf16(k4.x, k4.y, hw.x, lw.x);
            split_pack_bf16(k4.z, k4.w, hw.y, lw.y);
            *(uint2*)&Kh[r*WPD + (c >> 1)] = hw;
            *(uint2*)&Kl[r*WPD + (c >> 1)] = lw;
            // V: column-wise thread mapping -> conflict-free transposed STS
            int rv = f & 63, cv = (f >> 6) << 2;
            float4 vv = *(const float4*)(Vb + rv * DKQ + cv);
            Vt[(cv+0)*PAD + rv] = f2tf32(vv.x);
            Vt[(cv+1)*PAD + rv] = f2tf32(vv.y);
            Vt[(cv+2)*PAD + rv] = f2tf32(vv.z);
            Vt[(cv+3)*PAD + rv] = f2tf32(vv.w);
        }
        __syncthreads();

        // ---- scores: bf16x2 QK^T (3 mma per k16 step) ----
        float accS[8][4];
#pragma unroll
        for (int nf = 0; nf < 8; nf++)
#pragma unroll
            for (int i = 0; i < 4; i++) accS[nf][i] = 0.f;

#pragma unroll
        for (int ks = 0; ks < 4; ks++) {
            const int k8 = ks * 8;             // word offset for k16 step
            uint32_t ah0 = Qh[qbw + k8 + lc];
            uint32_t ah1 = Qh[qbw + 8*WPD + k8 + lc];
            uint32_t ah2 = Qh[qbw + k8 + lc + 4];
            uint32_t ah3 = Qh[qbw + 8*WPD + k8 + lc + 4];
            uint32_t al0 = Ql[qbw + k8 + lc];
            uint32_t al1 = Ql[qbw + 8*WPD + k8 + lc];
            uint32_t al2 = Ql[qbw + k8 + lc + 4];
            uint32_t al3 = Ql[qbw + 8*WPD + k8 + lc + 4];
#pragma unroll
            for (int nf = 0; nf < 8; nf++) {
                int nb = (nf*8 + lr) * WPD + k8 + lc;
                uint32_t bh0 = Kh[nb], bh1 = Kh[nb + 4];
                uint32_t bl0 = Kl[nb], bl1 = Kl[nb + 4];
                mma_bf16(accS[nf][0], accS[nf][1], accS[nf][2], accS[nf][3],
                         ah0, ah1, ah2, ah3, bh0, bh1);
                mma_bf16(accS[nf][0], accS[nf][1], accS[nf][2], accS[nf][3],
                         ah0, ah1, ah2, ah3, bl0, bl1);
                mma_bf16(accS[nf][0], accS[nf][1], accS[nf][2], accS[nf][3],
                         al0, al1, al2, al3, bh0, bh1);
            }
        }

        // ---- causal mask on diagonal tile ----
        if (kt == qt) {
#pragma unroll
            for (int nf = 0; nf < 8; nf++) {
                int gc = kt*64 + nf*8 + 2*lc;
                if (gc     > qrow0)     accS[nf][0] = -1e30f;
                if (gc + 1 > qrow0)     accS[nf][1] = -1e30f;
                if (gc     > qrow0 + 8) accS[nf][2] = -1e30f;
                if (gc + 1 > qrow0 + 8) accS[nf][3] = -1e30f;
            }
        }

        // ---- online softmax (two row-halves per thread) ----
#pragma unroll
        for (int h = 0; h < 2; h++) {
            const int i0 = 2*h, i1 = 2*h + 1;
            float rmax = accS[0][i0];
#pragma unroll
            for (int nf = 0; nf < 8; nf++) {
                rmax = fmaxf(rmax, accS[nf][i0]);
                rmax = fmaxf(rmax, accS[nf][i1]);
            }
            rmax = fmaxf(rmax, __shfl_xor_sync(0xffffffffu, rmax, 1));
            rmax = fmaxf(rmax, __shfl_xor_sync(0xffffffffu, rmax, 2));
            float mn   = fmaxf(mrow[h], rmax);
            float corr = __expf(mrow[h] - mn);
            mrow[h] = mn;
            float rsum = 0.f;
            const int pb = qbp + h*8*PAD;
#pragma unroll
            for (int nf = 0; nf < 8; nf++) {
                uint32_t u0 = f2tf32(__expf(accS[nf][i0] - mn));
                uint32_t u1 = f2tf32(__expf(accS[nf][i1] - mn));
                rsum += __uint_as_float(u0) + __uint_as_float(u1);
                uint2 pp = { u0, u1 };
                *(uint2*)&Ps[pb + nf*8 + 2*lc] = pp;
                accO[nf][i0] *= corr;
                accO[nf][i1] *= corr;
            }
            rsum += __shfl_xor_sync(0xffffffffu, rsum, 1);
            rsum += __shfl_xor_sync(0xffffffffu, rsum, 2);
            lrow[h] = lrow[h] * corr + rsum;
        }
        __syncwarp();   // P rows are produced & consumed by this warp only

        // ---- accO += P @ V (plain tf32 m16n8k8) ----
#pragma unroll
        for (int ks = 0; ks < 8; ks++) {
            const int k8 = ks * 8;
            uint32_t a0 = Ps[qbp + k8 + lc];
            uint32_t a2 = Ps[qbp + k8 + lc + 4];
            uint32_t a1 = Ps[qbp + 8*PAD + k8 + lc];
            uint32_t a3 = Ps[qbp + 8*PAD + k8 + lc + 4];
#pragma unroll
            for (int nf = 0; nf < 8; nf++) {
                int nb = (nf*8 + lr) * PAD + k8 + lc;
                uint32_t b0 = Vt[nb], b1 = Vt[nb + 4];
                mma_tf32(accO[nf][0], accO[nf][1], accO[nf][2], accO[nf][3],
                         a0, a1, a2, a3, b0, b1);
            }
        }
    }

    // ---- epilogue: out[B,S,D] ----
    const int b = bh >> 4, h = bh & 15;
    const float inv0 = 1.f / lrow[0];
    const float inv1 = 1.f / lrow[1];
    const int s0 = qt*64 + w*16 + lr;
    const int s1 = s0 + 8;
#pragma unroll
    for (int nf = 0; nf < 8; nf++) {
        int col = h*DKQ + nf*8 + 2*lc;
        float2 v0 = { accO[nf][0] * inv0, accO[nf][1] * inv0 };
        float2 v1 = { accO[nf][2] * inv1, accO[nf][3] * inv1 };
        *(float2*)(out + ((size_t)b * SLEN + s0) * DDIM + col) = v0;
        *(float2*)(out + ((size_t)b * SLEN + s1) * DDIM + col) = v1;
    }
}

extern "C" void kernel_launch(void* const* d_in, const int* in_sizes, int n_in,
                              void* d_out, int out_size) {
    const float* q  = (const float*)d_in[0];
    const float* k  = (const float*)d_in[1];
    const float* v  = (const float*)d_in[2];
    const float* Wq = (const float*)d_in[3];
    const float* bq = (const float*)d_in[4];
    const float* Wk = (const float*)d_in[5];
    const float* bk = (const float*)d_in[6];
    const float* Wv = (const float*)d_in[7];
    const float* bv = (const float*)d_in[8];
    float* out = (float*)d_out;

    float *gq, *gk, *gv, *gwt;
    cudaGetSymbolAddress((void**)&gq, g_q);
    cudaGetSymbolAddress((void**)&gk, g_k);
    cudaGetSymbolAddress((void**)&gv, g_v);
    cudaGetSymbolAddress((void**)&gwt, g_wt);

    dim3 tgrid(DDIM/32, DDIM/32), tblk(32, 8);
    transpose_kernel<<<tgrid, tblk>>>(Wq, gwt + 0*DDIM*DDIM);
    transpose_kernel<<<tgrid, tblk>>>(Wk, gwt + 1*DDIM*DDIM);
    transpose_kernel<<<tgrid, tblk>>>(Wv, gwt + 2*DDIM*DDIM);

    // 3 projections in one launch (z selects Q/K/V).
    dim3 pgrid(DDIM/128, (BNUM*SLEN)/128, 3);
    proj_mma_kernel<<<pgrid, 256>>>(
        q, k, v,
        gwt + 0*DDIM*DDIM, gwt + 1*DDIM*DDIM, gwt + 2*DDIM*DDIM,
        bq, bk, bv,
        gq, gk, gv);

    const int attn_smem = (4*64*WPD + 2*64*PAD) * 4;   // 71680 bytes
    cudaFuncSetAttribute(attn_mma_kernel,
                         cudaFuncAttributeMaxDynamicSharedMemorySize, attn_smem);
    attn_mma_kernel<<<dim3(BNUM*HNUM, SLEN/64), 128, attn_smem>>>(gq, gk, gv, out);
}

// round 7
// speedup vs baseline: 1.6183x; 1.0650x over previous
#include <cuda_runtime.h>
#include <cuda_bf16.h>
#include <cuda_fp16.h>
#include <cstdint>

#define BNUM 2
#define SLEN 2048
#define DDIM 1024
#define HNUM 16
#define DKQ  64
#define WPD  36   // word pitch: 32 data words + 4 pad (conflict-free)

// Scratch: projected Q/K/V in [B, H, S, DK] fp32 + transposed tf32 weights [N, K].
__device__ float g_q[BNUM*HNUM*SLEN*DKQ];
__device__ float g_k[BNUM*HNUM*SLEN*DKQ];
__device__ float g_v[BNUM*HNUM*SLEN*DKQ];
__device__ float g_wt[3][DDIM*DDIM];

// ---------------- helpers ----------------
__device__ __forceinline__ uint32_t f2tf32(float x) {
    uint32_t y;
    asm("cvt.rna.tf32.f32 %0, %1;" : "=r"(y) : "f"(x));
    return y;
}
__device__ __forceinline__ uint32_t smem_u32(const void* p) {
    uint32_t a;
    asm("{ .reg .u64 t; cvta.to.shared.u64 t, %1; cvt.u32.u64 %0, t; }"
        : "=r"(a) : "l"(p));
    return a;
}
__device__ __forceinline__ void cp16(uint32_t dst, const void* src) {
    asm volatile("cp.async.cg.shared.global [%0], [%1], 16;"
                 :: "r"(dst), "l"(src));
}
#define CP_COMMIT() asm volatile("cp.async.commit_group;" ::: "memory")
#define CP_WAIT1()  asm volatile("cp.async.wait_group 1;" ::: "memory")
#define CP_WAIT0()  asm volatile("cp.async.wait_group 0;" ::: "memory")

__device__ __forceinline__ void mma_tf32(
    float& d0, float& d1, float& d2, float& d3,
    uint32_t a0, uint32_t a1, uint32_t a2, uint32_t a3,
    uint32_t b0, uint32_t b1)
{
    asm volatile(
        "mma.sync.aligned.m16n8k8.row.col.f32.tf32.tf32.f32 "
        "{%0,%1,%2,%3}, {%4,%5,%6,%7}, {%8,%9}, {%0,%1,%2,%3};"
        : "+f"(d0), "+f"(d1), "+f"(d2), "+f"(d3)
        : "r"(a0), "r"(a1), "r"(a2), "r"(a3), "r"(b0), "r"(b1));
}
__device__ __forceinline__ void mma_bf16(
    float& d0, float& d1, float& d2, float& d3,
    uint32_t a0, uint32_t a1, uint32_t a2, uint32_t a3,
    uint32_t b0, uint32_t b1)
{
    asm volatile(
        "mma.sync.aligned.m16n8k16.row.col.f32.bf16.bf16.f32 "
        "{%0,%1,%2,%3}, {%4,%5,%6,%7}, {%8,%9}, {%0,%1,%2,%3};"
        : "+f"(d0), "+f"(d1), "+f"(d2), "+f"(d3)
        : "r"(a0), "r"(a1), "r"(a2), "r"(a3), "r"(b0), "r"(b1));
}
__device__ __forceinline__ void mma_fp16(
    float& d0, float& d1, float& d2, float& d3,
    uint32_t a0, uint32_t a1, uint32_t a2, uint32_t a3,
    uint32_t b0, uint32_t b1)
{
    asm volatile(
        "mma.sync.aligned.m16n8k16.row.col.f32.f16.f16.f32 "
        "{%0,%1,%2,%3}, {%4,%5,%6,%7}, {%8,%9}, {%0,%1,%2,%3};"
        : "+f"(d0), "+f"(d1), "+f"(d2), "+f"(d3)
        : "r"(a0), "r"(a1), "r"(a2), "r"(a3), "r"(b0), "r"(b1));
}
__device__ __forceinline__ void split_pack_bf16(
    float x0, float x1, uint32_t& whi, uint32_t& wlo)
{
    __nv_bfloat16 h0 = __float2bfloat16(x0);
    __nv_bfloat16 h1 = __float2bfloat16(x1);
    float r0 = x0 - __bfloat162float(h0);
    float r1 = x1 - __bfloat162float(h1);
    __nv_bfloat16 l0 = __float2bfloat16(r0);
    __nv_bfloat16 l1 = __float2bfloat16(r1);
    whi = (uint32_t)__bfloat16_as_ushort(h0) |
          ((uint32_t)__bfloat16_as_ushort(h1) << 16);
    wlo = (uint32_t)__bfloat16_as_ushort(l0) |
          ((uint32_t)__bfloat16_as_ushort(l1) << 16);
}
__device__ __forceinline__ uint32_t pack_h2(float a, float b) {
    __half2 h = __floats2half2_rn(a, b);
    return *(uint32_t*)&h;
}

// ---------------- weight transpose + tf32 round: Wt[n][k] = tf32(W[k][n]) ----------------
__global__ __launch_bounds__(256) void transpose_kernel(
    const float* __restrict__ in, float* __restrict__ out)
{
    __shared__ float t[32][33];
    int x = blockIdx.x*32 + threadIdx.x;
    int y0 = blockIdx.y*32 + threadIdx.y;
#pragma unroll
    for (int j = 0; j < 32; j += 8)
        t[threadIdx.y + j][threadIdx.x] = in[(size_t)(y0 + j)*DDIM + x];
    __syncthreads();
    int xo = blockIdx.y*32 + threadIdx.x;
    int yo = blockIdx.x*32 + threadIdx.y;
#pragma unroll
    for (int j = 0; j < 32; j += 8)
        out[(size_t)(yo + j)*DDIM + xo] =
            __uint_as_float(f2tf32(t[threadIdx.x][threadIdx.y + j]));
}

// ---------------- cp.async tf32 HMMA projection, 3 GEMMs merged on z ----------------
// Tile 128x128, K-chunk 32, 2-stage smem pipeline. A fragments cvt.rna'd after
// LDS (activations are raw fp32); W pre-rounded to tf32 -> no B cvt needed.
__global__ __launch_bounds__(256, 2) void proj_mma_kernel(
    const float* __restrict__ A0, const float* __restrict__ A1, const float* __restrict__ A2,
    const float* __restrict__ W0, const float* __restrict__ W1, const float* __restrict__ W2,
    const float* __restrict__ bias0, const float* __restrict__ bias1, const float* __restrict__ bias2,
    float* __restrict__ o0, float* __restrict__ o1, float* __restrict__ o2)
{
    extern __shared__ uint32_t psm[];        // As[2][128][36] | Bs[2][128][36]
    uint32_t* As = psm;
    uint32_t* Bs = psm + 2*128*36;
    const uint32_t as_u = smem_u32(As);
    const uint32_t bs_u = smem_u32(Bs);

    const int z = blockIdx.z;
    const float* A    = (z == 0) ? A0 : (z == 1) ? A1 : A2;
    const float* Wt   = (z == 0) ? W0 : (z == 1) ? W1 : W2;
    const float* bias = (z == 0) ? bias0 : (z == 1) ? bias1 : bias2;
    float*       out  = (z == 0) ? o0 : (z == 1) ? o1 : o2;

    const int tid  = threadIdx.x;
    const int wid  = tid >> 5;
    const int lane = tid & 31;
    const int lr   = lane >> 2;
    const int lc   = lane & 3;
    const int wm   = (wid >> 2) * 64;
    const int wn   = (wid & 3) * 32;
    const int col0 = blockIdx.x << 7;
    const int row0 = blockIdx.y << 7;

    const float* Abase = A  + (size_t)row0 * DDIM;
    const float* Bbase = Wt + (size_t)col0 * DDIM;

    auto issue = [&](int c, int s) {
#pragma unroll
        for (int it = 0; it < 4; it++) {
            int f = tid + it * 256;          // 0..1023
            int r = f >> 3;
            int o = (f & 7) * 16;            // byte offset within 128B row
            uint32_t d = (uint32_t)((s*128 + r) * 144) + o;
            cp16(as_u + d, (const char*)(Abase + (size_t)r * DDIM + c*32) + o);
            cp16(bs_u + d, (const char*)(Bbase + (size_t)r * DDIM + c*32) + o);
        }
    };

    float acc[4][4][4];
#pragma unroll
    for (int mt = 0; mt < 4; mt++)
#pragma unroll
        for (int nt = 0; nt < 4; nt++)
#pragma unroll
            for (int i = 0; i < 4; i++) acc[mt][nt][i] = 0.f;

    issue(0, 0); CP_COMMIT();

    for (int c = 0; c < 32; c++) {
        const int s = c & 1;
        __syncthreads();                      // prior readers of stage s^1 done
        if (c < 31) { issue(c + 1, s ^ 1); CP_COMMIT(); CP_WAIT1(); }
        else        { CP_WAIT0(); }
        __syncthreads();                      // stage s visible to all

        const uint32_t* Ast = As + s*128*36;
        const uint32_t* Bst = Bs + s*128*36;
#pragma unroll
        for (int ks = 0; ks < 4; ks++) {
            const int k8 = ks * 8;
            uint32_t a[4][4];
#pragma unroll
            for (int mt = 0; mt < 4; mt++) {
                int r = wm + mt * 16 + lr;
                a[mt][0] = f2tf32(__uint_as_float(Ast[r*36 + k8 + lc]));
                a[mt][1] = f2tf32(__uint_as_float(Ast[(r+8)*36 + k8 + lc]));
                a[mt][2] = f2tf32(__uint_as_float(Ast[r*36 + k8 + lc + 4]));
                a[mt][3] = f2tf32(__uint_as_float(Ast[(r+8)*36 + k8 + lc + 4]));
            }
#pragma unroll
            for (int nt = 0; nt < 4; nt++) {
                int n = wn + nt * 8 + lr;
                uint32_t b0 = Bst[n*36 + k8 + lc];       // already tf32
                uint32_t b1 = Bst[n*36 + k8 + lc + 4];
#pragma unroll
                for (int mt = 0; mt < 4; mt++)
                    mma_tf32(acc[mt][nt][0], acc[mt][nt][1],
                             acc[mt][nt][2], acc[mt][nt][3],
                             a[mt][0], a[mt][1], a[mt][2], a[mt][3], b0, b1);
            }
        }
    }

#pragma unroll
    for (int mt = 0; mt < 4; mt++) {
#pragma unroll
        for (int nt = 0; nt < 4; nt++) {
            int row = row0 + wm + mt * 16 + lr;
            int col = col0 + wn + nt * 8 + 2 * lc;
            float2 bb = *(const float2*)(bias + col);
            int head = col >> 6;
            int dk   = col & 63;
            int b0i  = row >> 11;
            int s0   = row & (SLEN - 1);
            float2 v0 = { acc[mt][nt][0] + bb.x, acc[mt][nt][1] + bb.y };
            *(float2*)(out + ((size_t)(b0i * HNUM + head) * SLEN + s0) * DKQ + dk) = v0;
            int row2 = row + 8;
            int b1i  = row2 >> 11;
            int s1   = row2 & (SLEN - 1);
            float2 v1 = { acc[mt][nt][2] + bb.x, acc[mt][nt][3] + bb.y };
            *(float2*)(out + ((size_t)(b1i * HNUM + head) * SLEN + s1) * DKQ + dk) = v1;
        }
    }
}

// ---------------- tensor-core flash attention ----------------
// QK^T: bf16x2 m16n8k16 (hi*hi + hi*lo + lo*hi). PV: fp16 m16n8k16
// (fp16 mantissa == tf32 mantissa; P in [0,1], V small -> exact-range safe).
__global__ __launch_bounds__(128) void attn_mma_kernel(
    const float* __restrict__ Q, const float* __restrict__ K,
    const float* __restrict__ V, float* __restrict__ out)
{
    extern __shared__ uint32_t sm[];
    uint32_t* Qh  = sm;                     // [64][WPD] bf16x2, 2 d / word
    uint32_t* Ql  = sm + 64*WPD;
    uint32_t* Kh  = sm + 2*64*WPD;
    uint32_t* Kl  = sm + 3*64*WPD;
    uint32_t* Vt2 = sm + 4*64*WPD;          // [64 d][WPD] fp16x2, 2 keys / word
    uint32_t* Ps2 = sm + 5*64*WPD;          // [64 q][WPD] fp16x2, 2 keys / word

    const int tid  = threadIdx.x;
    const int w    = tid >> 5;
    const int lane = tid & 31;
    const int lr   = lane >> 2;
    const int lc   = lane & 3;
    const int bh   = blockIdx.x;
    const int qt   = (gridDim.y - 1) - blockIdx.y;  // big tiles first

    // Load Q tile, pre-scaled by 0.125, split+pack bf16x2.
    const float* Qb = Q + ((size_t)bh * SLEN + (size_t)qt * 64) * DKQ;
#pragma unroll
    for (int it = 0; it < 8; it++) {
        int f = tid + it * 128;
        int r = f >> 4, c = (f & 15) << 2;
        float4 v4 = *(const float4*)(Qb + r * DKQ + c);
        v4.x *= 0.125f; v4.y *= 0.125f; v4.z *= 0.125f; v4.w *= 0.125f;
        uint2 hw, lw;
        split_pack_bf16(v4.x, v4.y, hw.x, lw.x);
        split_pack_bf16(v4.z, v4.w, hw.y, lw.y);
        *(uint2*)&Qh[r*WPD + (c >> 1)] = hw;
        *(uint2*)&Ql[r*WPD + (c >> 1)] = lw;
    }

    float accO[8][4];
#pragma unroll
    for (int nf = 0; nf < 8; nf++)
#pragma unroll
        for (int i = 0; i < 4; i++) accO[nf][i] = 0.f;
    float mrow[2] = { -1e30f, -1e30f };
    float lrow[2] = { 0.f, 0.f };

    const int qrow0 = qt*64 + w*16 + lr;
    const int qbw   = (w*16 + lr) * WPD;

    for (int kt = 0; kt <= qt; kt++) {
        __syncthreads();
        const float* Kb = K + ((size_t)bh * SLEN + (size_t)kt * 64) * DKQ;
        const float* Vb = V + ((size_t)bh * SLEN + (size_t)kt * 64) * DKQ;
#pragma unroll
        for (int it = 0; it < 8; it++) {
            int f = tid + it * 128;
            int r = f >> 4, c = (f & 15) << 2;
            float4 k4 = *(const float4*)(Kb + r * DKQ + c);
            uint2 hw, lw;
            split_pack_bf16(k4.x, k4.y, hw.x, lw.x);
            split_pack_bf16(k4.z, k4.w, hw.y, lw.y);
            *(uint2*)&Kh[r*WPD + (c >> 1)] = hw;
            *(uint2*)&Kl[r*WPD + (c >> 1)] = lw;
            // V: load [key][4 d], pair adjacent keys via shuffle, store packed
            // fp16x2 (2 keys/word) transposed to [d][key-pair]. Conflict-free.
            int rv = f & 63, cv = (f >> 6) << 2;
            float4 vv = *(const float4*)(Vb + rv * DKQ + cv);
            float px = __shfl_xor_sync(0xffffffffu, vv.x, 1);
            float py = __shfl_xor_sync(0xffffffffu, vv.y, 1);
            float pz = __shfl_xor_sync(0xffffffffu, vv.z, 1);
            float pw = __shfl_xor_sync(0xffffffffu, vv.w, 1);
            int kw = rv >> 1;
            if (!(rv & 1)) {   // even key: own=low half, partner=high half
                Vt2[(cv+0)*WPD + kw] = pack_h2(vv.x, px);
                Vt2[(cv+1)*WPD + kw] = pack_h2(vv.y, py);
            } else {           // odd key: partner=low, own=high
                Vt2[(cv+2)*WPD + kw] = pack_h2(pz, vv.z);
                Vt2[(cv+3)*WPD + kw] = pack_h2(pw, vv.w);
            }
        }
        __syncthreads();

        // ---- scores: bf16x2 QK^T ----
        float accS[8][4];
#pragma unroll
        for (int nf = 0; nf < 8; nf++)
#pragma unroll
            for (int i = 0; i < 4; i++) accS[nf][i] = 0.f;

#pragma unroll
        for (int ks = 0; ks < 4; ks++) {
            const int k8 = ks * 8;
            uint32_t ah0 = Qh[qbw + k8 + lc];
            uint32_t ah1 = Qh[qbw + 8*WPD + k8 + lc];
            uint32_t ah2 = Qh[qbw + k8 + lc + 4];
            uint32_t ah3 = Qh[qbw + 8*WPD + k8 + lc + 4];
            uint32_t al0 = Ql[qbw + k8 + lc];
            uint32_t al1 = Ql[qbw + 8*WPD + k8 + lc];
            uint32_t al2 = Ql[qbw + k8 + lc + 4];
            uint32_t al3 = Ql[qbw + 8*WPD + k8 + lc + 4];
#pragma unroll
            for (int nf = 0; nf < 8; nf++) {
                int nb = (nf*8 + lr) * WPD + k8 + lc;
                uint32_t bh0 = Kh[nb], bh1 = Kh[nb + 4];
                uint32_t bl0 = Kl[nb], bl1 = Kl[nb + 4];
                mma_bf16(accS[nf][0], accS[nf][1], accS[nf][2], accS[nf][3],
                         ah0, ah1, ah2, ah3, bh0, bh1);
                mma_bf16(accS[nf][0], accS[nf][1], accS[nf][2], accS[nf][3],
                         ah0, ah1, ah2, ah3, bl0, bl1);
                mma_bf16(accS[nf][0], accS[nf][1], accS[nf][2], accS[nf][3],
                         al0, al1, al2, al3, bh0, bh1);
            }
        }

        // ---- causal mask on diagonal tile ----
        if (kt == qt) {
#pragma unroll
            for (int nf = 0; nf < 8; nf++) {
                int gc = kt*64 + nf*8 + 2*lc;
                if (gc     > qrow0)     accS[nf][0] = -1e30f;
                if (gc + 1 > qrow0)     accS[nf][1] = -1e30f;
                if (gc     > qrow0 + 8) accS[nf][2] = -1e30f;
                if (gc + 1 > qrow0 + 8) accS[nf][3] = -1e30f;
            }
        }

        // ---- online softmax; P packed fp16x2 straight into smem ----
#pragma unroll
        for (int h = 0; h < 2; h++) {
            const int i0 = 2*h, i1 = 2*h + 1;
            float rmax = accS[0][i0];
#pragma unroll
            for (int nf = 0; nf < 8; nf++) {
                rmax = fmaxf(rmax, accS[nf][i0]);
                rmax = fmaxf(rmax, accS[nf][i1]);
            }
            rmax = fmaxf(rmax, __shfl_xor_sync(0xffffffffu, rmax, 1));
            rmax = fmaxf(rmax, __shfl_xor_sync(0xffffffffu, rmax, 2));
            float mn   = fmaxf(mrow[h], rmax);
            float corr = __expf(mrow[h] - mn);
            mrow[h] = mn;
            float rsum = 0.f;
            const int pb = qbw + h*8*WPD;
#pragma unroll
            for (int nf = 0; nf < 8; nf++) {
                float e0 = __expf(accS[nf][i0] - mn);
                float e1 = __expf(accS[nf][i1] - mn);
                __half2 hp = __floats2half2_rn(e0, e1);
                Ps2[pb + nf*4 + lc] = *(uint32_t*)&hp;
                rsum += __low2float(hp) + __high2float(hp);  // sum rounded P
                accO[nf][i0] *= corr;
                accO[nf][i1] *= corr;
            }
            rsum += __shfl_xor_sync(0xffffffffu, rsum, 1);
            rsum += __shfl_xor_sync(0xffffffffu, rsum, 2);
            lrow[h] = lrow[h] * corr + rsum;
        }
        __syncwarp();   // P rows produced & consumed within this warp only

        // ---- accO += P @ V (fp16 m16n8k16) ----
#pragma unroll
        for (int ks = 0; ks < 4; ks++) {
            const int k8 = ks * 8;
            uint32_t a0 = Ps2[qbw + k8 + lc];
            uint32_t a1 = Ps2[qbw + 8*WPD + k8 + lc];
            uint32_t a2 = Ps2[qbw + k8 + lc + 4];
            uint32_t a3 = Ps2[qbw + 8*WPD + k8 + lc + 4];
#pragma unroll
            for (int nf = 0; nf < 8; nf++) {
                int nb = (nf*8 + lr) * WPD + k8 + lc;
                uint32_t b0 = Vt2[nb], b1 = Vt2[nb + 4];
                mma_fp16(accO[nf][0], accO[nf][1], accO[nf][2], accO[nf][3],
                         a0, a1, a2, a3, b0, b1);
            }
        }
    }

    // ---- epilogue: out[B,S,D] ----
    const int b = bh >> 4, h = bh & 15;
    const float inv0 = 1.f / lrow[0];
    const float inv1 = 1.f / lrow[1];
    const int s0 = qt*64 + w*16 + lr;
    const int s1 = s0 + 8;
#pragma unroll
    for (int nf = 0; nf < 8; nf++) {
        int col = h*DKQ + nf*8 + 2*lc;
        float2 v0 = { accO[nf][0] * inv0, accO[nf][1] * inv0 };
        float2 v1 = { accO[nf][2] * inv1, accO[nf][3] * inv1 };
        *(float2*)(out + ((size_t)b * SLEN + s0) * DDIM + col) = v0;
        *(float2*)(out + ((size_t)b * SLEN + s1) * DDIM + col) = v1;
    }
}

extern "C" void kernel_launch(void* const* d_in, const int* in_sizes, int n_in,
                              void* d_out, int out_size) {
    const float* q  = (const float*)d_in[0];
    const float* k  = (const float*)d_in[1];
    const float* v  = (const float*)d_in[2];
    const float* Wq = (const float*)d_in[3];
    const float* bq = (const float*)d_in[4];
    const float* Wk = (const float*)d_in[5];
    const float* bk = (const float*)d_in[6];
    const float* Wv = (const float*)d_in[7];
    const float* bv = (const float*)d_in[8];
    float* out = (float*)d_out;

    float *gq, *gk, *gv, *gwt;
    cudaGetSymbolAddress((void**)&gq, g_q);
    cudaGetSymbolAddress((void**)&gk, g_k);
    cudaGetSymbolAddress((void**)&gv, g_v);
    cudaGetSymbolAddress((void**)&gwt, g_wt);

    dim3 tgrid(DDIM/32, DDIM/32), tblk(32, 8);
    transpose_kernel<<<tgrid, tblk>>>(Wq, gwt + 0*DDIM*DDIM);
    transpose_kernel<<<tgrid, tblk>>>(Wk, gwt + 1*DDIM*DDIM);
    transpose_kernel<<<tgrid, tblk>>>(Wv, gwt + 2*DDIM*DDIM);

    const int proj_smem = 2 * 2 * 128 * 36 * 4;   // 73728
    cudaFuncSetAttribute(proj_mma_kernel,
        cudaFuncAttributeMaxDynamicSharedMemorySize, proj_smem);
    dim3 pgrid(DDIM/128, (BNUM*SLEN)/128, 3);
    proj_mma_kernel<<<pgrid, 256, proj_smem>>>(
        q, k, v,
        gwt + 0*DDIM*DDIM, gwt + 1*DDIM*DDIM, gwt + 2*DDIM*DDIM,
        bq, bk, bv,
        gq, gk, gv);

    const int attn_smem = 6 * 64 * WPD * 4;       // 55296 bytes
    cudaFuncSetAttribute(attn_mma_kernel,
        cudaFuncAttributeMaxDynamicSharedMemorySize, attn_smem);
    attn_mma_kernel<<<dim3(BNUM*HNUM, SLEN/64), 128, attn_smem>>>(gq, gk, gv, out);
}

// round 8
// speedup vs baseline: 2.3716x; 1.4655x over previous
#include <cuda_runtime.h>
#include <cuda_bf16.h>
#include <cuda_fp16.h>
#include <cstdint>

#define BNUM 2
#define SLEN 2048
#define DDIM 1024
#define HNUM 16
#define DKQ  64
#define WPD  36     // attn word pitch: 32 data words + 4 pad (banks 4*lr+lc)
#define PPD  20     // proj word pitch: 16 data words + 4 pad (banks 20*lr+lc distinct)

// fp32 proj outputs [B,H,S,DK]
__device__ float    g_q[BNUM*HNUM*SLEN*DKQ];
__device__ float    g_k[BNUM*HNUM*SLEN*DKQ];
__device__ float    g_v[BNUM*HNUM*SLEN*DKQ];
__device__ float    g_wt[3][DDIM*DDIM];              // transposed W (fp32, exact)
__device__ uint32_t g_wt16[3][DDIM*DDIM/2];          // packed fp16 Wt[n][k]
__device__ uint32_t g_af16[3][BNUM*SLEN*DDIM/2];     // packed fp16 inputs
// attention-ready tiles
__device__ uint32_t g_qhi[BNUM*HNUM*SLEN*DKQ/2];     // bf16x2 hi, Q*0.125
__device__ uint32_t g_qlo[BNUM*HNUM*SLEN*DKQ/2];
__device__ uint32_t g_khi[BNUM*HNUM*SLEN*DKQ/2];
__device__ uint32_t g_klo[BNUM*HNUM*SLEN*DKQ/2];
__device__ uint32_t g_vt2[BNUM*HNUM*DKQ*SLEN/2];     // fp16x2 [bh][d][s_pair]

// ---------------- helpers ----------------
__device__ __forceinline__ uint32_t smem_u32(const void* p) {
    uint32_t a;
    asm("{ .reg .u64 t; cvta.to.shared.u64 t, %1; cvt.u32.u64 %0, t; }"
        : "=r"(a) : "l"(p));
    return a;
}
__device__ __forceinline__ void cp16(uint32_t dst, const void* src) {
    asm volatile("cp.async.cg.shared.global [%0], [%1], 16;"
                 :: "r"(dst), "l"(src));
}
#define CP_COMMIT() asm volatile("cp.async.commit_group;" ::: "memory")
#define CP_WAIT1()  asm volatile("cp.async.wait_group 1;" ::: "memory")
#define CP_WAIT0()  asm volatile("cp.async.wait_group 0;" ::: "memory")

__device__ __forceinline__ void mma_bf16(
    float& d0, float& d1, float& d2, float& d3,
    uint32_t a0, uint32_t a1, uint32_t a2, uint32_t a3,
    uint32_t b0, uint32_t b1)
{
    asm volatile(
        "mma.sync.aligned.m16n8k16.row.col.f32.bf16.bf16.f32 "
        "{%0,%1,%2,%3}, {%4,%5,%6,%7}, {%8,%9}, {%0,%1,%2,%3};"
        : "+f"(d0), "+f"(d1), "+f"(d2), "+f"(d3)
        : "r"(a0), "r"(a1), "r"(a2), "r"(a3), "r"(b0), "r"(b1));
}
__device__ __forceinline__ void mma_fp16(
    float& d0, float& d1, float& d2, float& d3,
    uint32_t a0, uint32_t a1, uint32_t a2, uint32_t a3,
    uint32_t b0, uint32_t b1)
{
    asm volatile(
        "mma.sync.aligned.m16n8k16.row.col.f32.f16.f16.f32 "
        "{%0,%1,%2,%3}, {%4,%5,%6,%7}, {%8,%9}, {%0,%1,%2,%3};"
        : "+f"(d0), "+f"(d1), "+f"(d2), "+f"(d3)
        : "r"(a0), "r"(a1), "r"(a2), "r"(a3), "r"(b0), "r"(b1));
}
__device__ __forceinline__ void split_pack_bf16(
    float x0, float x1, uint32_t& whi, uint32_t& wlo)
{
    __nv_bfloat16 h0 = __float2bfloat16(x0);
    __nv_bfloat16 h1 = __float2bfloat16(x1);
    float r0 = x0 - __bfloat162float(h0);
    float r1 = x1 - __bfloat162float(h1);
    __nv_bfloat16 l0 = __float2bfloat16(r0);
    __nv_bfloat16 l1 = __float2bfloat16(r1);
    whi = (uint32_t)__bfloat16_as_ushort(h0) |
          ((uint32_t)__bfloat16_as_ushort(h1) << 16);
    wlo = (uint32_t)__bfloat16_as_ushort(l0) |
          ((uint32_t)__bfloat16_as_ushort(l1) << 16);
}
__device__ __forceinline__ uint32_t pack_h2(float a, float b) {
    __half2 h = __floats2half2_rn(a, b);
    return *(uint32_t*)&h;
}

// ---------------- pre-pass: fp32 -> packed fp16 ----------------
__global__ __launch_bounds__(256) void cvt_f16_kernel(
    const float4* __restrict__ in, uint2* __restrict__ out, int n4)
{
    int i = blockIdx.x * blockDim.x + threadIdx.x;
    if (i < n4) {
        float4 v = in[i];
        uint2 o = { pack_h2(v.x, v.y), pack_h2(v.z, v.w) };
        out[i] = o;
    }
}

// ---------------- weight transpose (exact fp32): Wt[n][k] = W[k][n] ----------------
__global__ __launch_bounds__(256) void transpose_kernel(
    const float* __restrict__ in, float* __restrict__ out)
{
    __shared__ float t[32][33];
    int x = blockIdx.x*32 + threadIdx.x;
    int y0 = blockIdx.y*32 + threadIdx.y;
#pragma unroll
    for (int j = 0; j < 32; j += 8)
        t[threadIdx.y + j][threadIdx.x] = in[(size_t)(y0 + j)*DDIM + x];
    __syncthreads();
    int xo = blockIdx.y*32 + threadIdx.x;
    int yo = blockIdx.x*32 + threadIdx.y;
#pragma unroll
    for (int j = 0; j < 32; j += 8)
        out[(size_t)(yo + j)*DDIM + xo] = t[threadIdx.x][threadIdx.y + j];
}

// ---------------- pre-pass: split Q/K into packed bf16 hi/lo ----------------
__global__ __launch_bounds__(256) void split_qk_kernel(
    const float2* __restrict__ q_src, const float2* __restrict__ k_src,
    uint32_t* __restrict__ qhi, uint32_t* __restrict__ qlo,
    uint32_t* __restrict__ khi, uint32_t* __restrict__ klo, int nw)
{
    int i = blockIdx.x * blockDim.x + threadIdx.x;
    if (i >= nw) return;
    if (blockIdx.y == 0) {
        float2 v = q_src[i];
        split_pack_bf16(v.x * 0.125f, v.y * 0.125f, qhi[i], qlo[i]);
    } else {
        float2 v = k_src[i];
        split_pack_bf16(v.x, v.y, khi[i], klo[i]);
    }
}

// ---------------- pre-pass: V -> packed fp16x2 transposed [bh][d][s_pair] ----------------
__global__ __launch_bounds__(128) void vt_kernel(
    const float* __restrict__ V, uint32_t* __restrict__ vt2)
{
    __shared__ float sm[64*68];
    const int tid = threadIdx.x;
    const int bh  = blockIdx.x;
    const int st  = blockIdx.y;          // 64-key tile
    const float* Vb = V + ((size_t)bh * SLEN + (size_t)st * 64) * DKQ;
#pragma unroll
    for (int it = 0; it < 8; it++) {
        int f = tid + it * 128;
        int rv = f & 63, cv = (f >> 6) << 2;
        float4 vv = *(const float4*)(Vb + rv * DKQ + cv);
        sm[(cv+0)*68 + rv] = vv.x;
        sm[(cv+1)*68 + rv] = vv.y;
        sm[(cv+2)*68 + rv] = vv.z;
        sm[(cv+3)*68 + rv] = vv.w;
    }
    __syncthreads();
#pragma unroll
    for (int it = 0; it < 16; it++) {
        int f = tid + it * 128;          // 0..2047 = 64 d x 32 words
        int d = f >> 5, sw = f & 31;
        uint32_t w = pack_h2(sm[d*68 + 2*sw], sm[d*68 + 2*sw + 1]);
        vt2[((size_t)bh * DKQ + d) * (SLEN/2) + st * 32 + sw] = w;
    }
}

// ---------------- fp16 HMMA projection, 3 GEMMs merged on z ----------------
// C[4096,1024] = A @ Wt^T + bias (fp32 out). Tile 128x128, K-chunk 32,
// 2-stage cp.async pipeline, all operands packed fp16 (pitch PPD=20 words).
__global__ __launch_bounds__(256, 2) void proj_mma_kernel(
    const uint32_t* __restrict__ A0, const uint32_t* __restrict__ A1, const uint32_t* __restrict__ A2,
    const uint32_t* __restrict__ W0, const uint32_t* __restrict__ W1, const uint32_t* __restrict__ W2,
    const float* __restrict__ bias0, const float* __restrict__ bias1, const float* __restrict__ bias2,
    float* __restrict__ o0, float* __restrict__ o1, float* __restrict__ o2)
{
    extern __shared__ uint32_t psm[];        // As[2][128][PPD] | Bs[2][128][PPD]
    uint32_t* As = psm;
    uint32_t* Bs = psm + 2*128*PPD;
    const uint32_t as_u = smem_u32(As);
    const uint32_t bs_u = smem_u32(Bs);

    const int z = blockIdx.z;
    const uint32_t* A  = (z == 0) ? A0 : (z == 1) ? A1 : A2;
    const uint32_t* Wt = (z == 0) ? W0 : (z == 1) ? W1 : W2;
    const float* bias  = (z == 0) ? bias0 : (z == 1) ? bias1 : bias2;
    float*       out   = (z == 0) ? o0 : (z == 1) ? o1 : o2;

    const int tid  = threadIdx.x;
    const int wid  = tid >> 5;
    const int lane = tid & 31;
    const int lr   = lane >> 2;
    const int lc   = lane & 3;
    const int wm   = (wid >> 2) * 64;
    const int wn   = (wid & 3) * 32;
    const int col0 = blockIdx.x << 7;
    const int row0 = blockIdx.y << 7;

    const uint32_t* Abase = A  + (size_t)row0 * (DDIM/2);
    const uint32_t* Bbase = Wt + (size_t)col0 * (DDIM/2);

    auto issue = [&](int c, int s) {
#pragma unroll
        for (int it = 0; it < 2; it++) {
            int f = tid + it * 256;          // 0..511 : 128 rows x 4 cp16
            int r = f >> 2;
            int o = (f & 3) * 16;            // byte offset within 64B row
            uint32_t d = (uint32_t)((s*128 + r) * (PPD*4)) + o;
            cp16(as_u + d, (const char*)(Abase + (size_t)r * (DDIM/2) + c*16) + o);
            cp16(bs_u + d, (const char*)(Bbase + (size_t)r * (DDIM/2) + c*16) + o);
        }
    };

    float acc[4][4][4];
#pragma unroll
    for (int mt = 0; mt < 4; mt++)
#pragma unroll
        for (int nt = 0; nt < 4; nt++)
#pragma unroll
            for (int i = 0; i < 4; i++) acc[mt][nt][i] = 0.f;

    issue(0, 0); CP_COMMIT();

    for (int c = 0; c < 32; c++) {
        const int s = c & 1;
        __syncthreads();
        if (c < 31) { issue(c + 1, s ^ 1); CP_COMMIT(); CP_WAIT1(); }
        else        { CP_WAIT0(); }
        __syncthreads();

        const uint32_t* Ast = As + s*128*PPD;
        const uint32_t* Bst = Bs + s*128*PPD;
#pragma unroll
        for (int ks = 0; ks < 2; ks++) {     // two k16 steps per 32-chunk
            const int k8 = ks * 8;
            uint32_t a[4][4];
#pragma unroll
            for (int mt = 0; mt < 4; mt++) {
                int r = wm + mt * 16 + lr;
                a[mt][0] = Ast[r*PPD + k8 + lc];
                a[mt][1] = Ast[(r+8)*PPD + k8 + lc];
                a[mt][2] = Ast[r*PPD + k8 + lc + 4];
                a[mt][3] = Ast[(r+8)*PPD + k8 + lc + 4];
            }
#pragma unroll
            for (int nt = 0; nt < 4; nt++) {
                int n = wn + nt * 8 + lr;
                uint32_t b0 = Bst[n*PPD + k8 + lc];
                uint32_t b1 = Bst[n*PPD + k8 + lc + 4];
#pragma unroll
                for (int mt = 0; mt < 4; mt++)
                    mma_fp16(acc[mt][nt][0], acc[mt][nt][1],
                             acc[mt][nt][2], acc[mt][nt][3],
                             a[mt][0], a[mt][1], a[mt][2], a[mt][3], b0, b1);
            }
        }
    }

#pragma unroll
    for (int mt = 0; mt < 4; mt++) {
#pragma unroll
        for (int nt = 0; nt < 4; nt++) {
            int col = col0 + wn + nt * 8 + 2 * lc;
            float2 bb = *(const float2*)(bias + col);
            int head = col >> 6;
            int dk   = col & 63;
#pragma unroll
            for (int h = 0; h < 2; h++) {
                int row = row0 + wm + mt * 16 + lr + h * 8;
                int bi  = row >> 11;
                int si  = row & (SLEN - 1);
                float2 v = { acc[mt][nt][2*h + 0] + bb.x,
                             acc[mt][nt][2*h + 1] + bb.y };
                *(float2*)(out + ((size_t)(bi * HNUM + head) * SLEN + si) * DKQ + dk) = v;
            }
        }
    }
}

// ---------------- cp.async pipelined tensor-core flash attention ----------------
// All operands pre-packed in global. QK^T: bf16x2 m16n8k16. PV: fp16 m16n8k16.
// 2-stage K/V pipeline. Smem word offsets:
//   Qh 0 | Ql 2304 | stage s: Kh 4608+6912s, Kl +2304, Vt +4608 | Ps 18432
__global__ __launch_bounds__(128) void attn_mma_kernel(
    const uint32_t* __restrict__ Qhi_g, const uint32_t* __restrict__ Qlo_g,
    const uint32_t* __restrict__ Khi_g, const uint32_t* __restrict__ Klo_g,
    const uint32_t* __restrict__ Vt_g,  float* __restrict__ out)
{
    extern __shared__ uint32_t sm[];
    uint32_t* Qh = sm;
    uint32_t* Ql = sm + 2304;
    uint32_t* Ps = sm + 18432;
    const uint32_t sm_u = smem_u32(sm);

    const int tid  = threadIdx.x;
    const int w    = tid >> 5;
    const int lane = tid & 31;
    const int lr   = lane >> 2;
    const int lc   = lane & 3;
    const int bh   = blockIdx.x;
    const int qt   = (gridDim.y - 1) - blockIdx.y;

    const uint32_t* Qh_src = Qhi_g + ((size_t)bh * SLEN + (size_t)qt * 64) * 32;
    const uint32_t* Ql_src = Qlo_g + ((size_t)bh * SLEN + (size_t)qt * 64) * 32;

    auto issue_kv = [&](int kt, int s) {
        const uint32_t* Kh_s = Khi_g + ((size_t)bh * SLEN + (size_t)kt * 64) * 32;
        const uint32_t* Kl_s = Klo_g + ((size_t)bh * SLEN + (size_t)kt * 64) * 32;
        const uint32_t* Vt_s = Vt_g  + (size_t)bh * DKQ * (SLEN/2) + (size_t)kt * 32;
        const uint32_t kb = sm_u + (uint32_t)(4608 + s*6912) * 4;
#pragma unroll
        for (int it = 0; it < 4; it++) {
            int f = tid + it * 128;          // 0..511 : 64 rows x 8 cp16
            int r = f >> 3;
            int o = (f & 7) * 16;
            uint32_t d = (uint32_t)(r * (WPD*4)) + o;
            cp16(kb + d,            (const char*)(Kh_s + (size_t)r * 32) + o);
            cp16(kb + 2304*4 + d,   (const char*)(Kl_s + (size_t)r * 32) + o);
            cp16(kb + 4608*4 + d,   (const char*)(Vt_s + (size_t)r * (SLEN/2)) + o);
        }
    };

    // prologue: Q + stage0 K/V in one group
#pragma unroll
    for (int it = 0; it < 4; it++) {
        int f = tid + it * 128;
        int r = f >> 3;
        int o = (f & 7) * 16;
        uint32_t d = (uint32_t)(r * (WPD*4)) + o;
        cp16(sm_u + d,          (const char*)(Qh_src + (size_t)r * 32) + o);
        cp16(sm_u + 2304*4 + d, (const char*)(Ql_src + (size_t)r * 32) + o);
    }
    issue_kv(0, 0);
    CP_COMMIT();

    float accO[8][4];
#pragma unroll
    for (int nf = 0; nf < 8; nf++)
#pragma unroll
        for (int i = 0; i < 4; i++) accO[nf][i] = 0.f;
    float mrow[2] = { -1e30f, -1e30f };
    float lrow[2] = { 0.f, 0.f };

    const int qrow0 = qt*64 + w*16 + lr;
    const int qbw   = (w*16 + lr) * WPD;

    for (int kt = 0; kt <= qt; kt++) {
        const int s = kt & 1;
        __syncthreads();                     // stage-s^1 readers (kt-1) done
        if (kt < qt) { issue_kv(kt + 1, s ^ 1); CP_COMMIT(); CP_WAIT1(); }
        else         { CP_WAIT0(); }
        __syncthreads();                     // stage s (and Q at kt=0) visible

        const uint32_t* Khs = sm + 4608 + s*6912;
        const uint32_t* Kls = Khs + 2304;
        const uint32_t* Vts = Khs + 4608;

        // ---- scores: bf16x2 QK^T ----
        float accS[8][4];
#pragma unroll
        for (int nf = 0; nf < 8; nf++)
#pragma unroll
            for (int i = 0; i < 4; i++) accS[nf][i] = 0.f;

#pragma unroll
        for (int ks = 0; ks < 4; ks++) {
            const int k8 = ks * 8;
            uint32_t ah0 = Qh[qbw + k8 + lc];
            uint32_t ah1 = Qh[qbw + 8*WPD + k8 + lc];
            uint32_t ah2 = Qh[qbw + k8 + lc + 4];
            uint32_t ah3 = Qh[qbw + 8*WPD + k8 + lc + 4];
            uint32_t al0 = Ql[qbw + k8 + lc];
            uint32_t al1 = Ql[qbw + 8*WPD + k8 + lc];
            uint32_t al2 = Ql[qbw + k8 + lc + 4];
            uint32_t al3 = Ql[qbw + 8*WPD + k8 + lc + 4];
#pragma unroll
            for (int nf = 0; nf < 8; nf++) {
                int nb = (nf*8 + lr) * WPD + k8 + lc;
                uint32_t bh0 = Khs[nb], bh1 = Khs[nb + 4];
                uint32_t bl0 = Kls[nb], bl1 = Kls[nb + 4];
                mma_bf16(accS[nf][0], accS[nf][1], accS[nf][2], accS[nf][3],
                         ah0, ah1, ah2, ah3, bh0, bh1);
                mma_bf16(accS[nf][0], accS[nf][1], accS[nf][2], accS[nf][3],
                         ah0, ah1, ah2, ah3, bl0, bl1);
                mma_bf16(accS[nf][0], accS[nf][1], accS[nf][2], accS[nf][3],
                         al0, al1, al2, al3, bh0, bh1);
            }
        }

        if (kt == qt) {
#pragma unroll
            for (int nf = 0; nf < 8; nf++) {
                int gc = kt*64 + nf*8 + 2*lc;
                if (gc     > qrow0)     accS[nf][0] = -1e30f;
                if (gc + 1 > qrow0)     accS[nf][1] = -1e30f;
                if (gc     > qrow0 + 8) accS[nf][2] = -1e30f;
                if (gc + 1 > qrow0 + 8) accS[nf][3] = -1e30f;
            }
        }

        // ---- online softmax; P packed fp16x2 ----
#pragma unroll
        for (int h = 0; h < 2; h++) {
            const int i0 = 2*h, i1 = 2*h + 1;
            float rmax = accS[0][i0];
#pragma unroll
            for (int nf = 0; nf < 8; nf++) {
                rmax = fmaxf(rmax, accS[nf][i0]);
                rmax = fmaxf(rmax, accS[nf][i1]);
            }
            rmax = fmaxf(rmax, __shfl_xor_sync(0xffffffffu, rmax, 1));
            rmax = fmaxf(rmax, __shfl_xor_sync(0xffffffffu, rmax, 2));
            float mn   = fmaxf(mrow[h], rmax);
            float corr = __expf(mrow[h] - mn);
            mrow[h] = mn;
            float rsum = 0.f;
            const int pb = qbw + h*8*WPD;
#pragma unroll
            for (int nf = 0; nf < 8; nf++) {
                float e0 = __expf(accS[nf][i0] - mn);
                float e1 = __expf(accS[nf][i1] - mn);
                __half2 hp = __floats2half2_rn(e0, e1);
                Ps[pb + nf*4 + lc] = *(uint32_t*)&hp;
                rsum += __low2float(hp) + __high2float(hp);
                accO[nf][i0] *= corr;
                accO[nf][i1] *= corr;
            }
            rsum += __shfl_xor_sync(0xffffffffu, rsum, 1);
            rsum += __shfl_xor_sync(0xffffffffu, rsum, 2);
            lrow[h] = lrow[h] * corr + rsum;
        }
        __syncwarp();

        // ---- accO += P @ V (fp16) ----
#pragma unroll
        for (int ks = 0; ks < 4; ks++) {
            const int k8 = ks * 8;
            uint32_t a0 = Ps[qbw + k8 + lc];
            uint32_t a1 = Ps[qbw + 8*WPD + k8 + lc];
            uint32_t a2 = Ps[qbw + k8 + lc + 4];
            uint32_t a3 = Ps[qbw + 8*WPD + k8 + lc + 4];
#pragma unroll
            for (int nf = 0; nf < 8; nf++) {
                int nb = (nf*8 + lr) * WPD + k8 + lc;
                uint32_t b0 = Vts[nb], b1 = Vts[nb + 4];
                mma_fp16(accO[nf][0], accO[nf][1], accO[nf][2], accO[nf][3],
                         a0, a1, a2, a3, b0, b1);
            }
        }
    }

    // ---- epilogue: out[B,S,D] ----
    const int b = bh >> 4, h = bh & 15;
    const float inv0 = 1.f / lrow[0];
    const float inv1 = 1.f / lrow[1];
    const int s0 = qt*64 + w*16 + lr;
    const int s1 = s0 + 8;
#pragma unroll
    for (int nf = 0; nf < 8; nf++) {
        int col = h*DKQ + nf*8 + 2*lc;
        float2 v0 = { accO[nf][0] * inv0, accO[nf][1] * inv0 };
        float2 v1 = { accO[nf][2] * inv1, accO[nf][3] * inv1 };
        *(float2*)(out + ((size_t)b * SLEN + s0) * DDIM + col) = v0;
        *(float2*)(out + ((size_t)b * SLEN + s1) * DDIM + col) = v1;
    }
}

extern "C" void kernel_launch(void* const* d_in, const int* in_sizes, int n_in,
                              void* d_out, int out_size) {
    const float* q  = (const float*)d_in[0];
    const float* k  = (const float*)d_in[1];
    const float* v  = (const float*)d_in[2];
    const float* Wq = (const float*)d_in[3];
    const float* bq = (const float*)d_in[4];
    const float* Wk = (const float*)d_in[5];
    const float* bk = (const float*)d_in[6];
    const float* Wv = (const float*)d_in[7];
    const float* bv = (const float*)d_in[8];
    float* out = (float*)d_out;

    float *gq, *gk, *gv, *gwt;
    uint32_t *gwt16, *gaf16, *gqh, *gql, *gkh, *gkl, *gvt;
    cudaGetSymbolAddress((void**)&gq,    g_q);
    cudaGetSymbolAddress((void**)&gk,    g_k);
    cudaGetSymbolAddress((void**)&gv,    g_v);
    cudaGetSymbolAddress((void**)&gwt,   g_wt);
    cudaGetSymbolAddress((void**)&gwt16, g_wt16);
    cudaGetSymbolAddress((void**)&gaf16, g_af16);
    cudaGetSymbolAddress((void**)&gqh,   g_qhi);
    cudaGetSymbolAddress((void**)&gql,   g_qlo);
    cudaGetSymbolAddress((void**)&gkh,   g_khi);
    cudaGetSymbolAddress((void**)&gkl,   g_klo);
    cudaGetSymbolAddress((void**)&gvt,   g_vt2);

    // Weight transpose (exact) then fp16 pack; inputs fp16 pack.
    dim3 tgrid(DDIM/32, DDIM/32), tblk(32, 8);
    transpose_kernel<<<tgrid, tblk>>>(Wq, gwt + 0*DDIM*DDIM);
    transpose_kernel<<<tgrid, tblk>>>(Wk, gwt + 1*DDIM*DDIM);
    transpose_kernel<<<tgrid, tblk>>>(Wv, gwt + 2*DDIM*DDIM);

    const int nw4 = DDIM*DDIM/4;
    cvt_f16_kernel<<<(nw4+255)/256, 256>>>((const float4*)(gwt + 0*DDIM*DDIM), (uint2*)(gwt16 + 0*DDIM*DDIM/2), nw4);
    cvt_f16_kernel<<<(nw4+255)/256, 256>>>((const float4*)(gwt + 1*DDIM*DDIM), (uint2*)(gwt16 + 1*DDIM*DDIM/2), nw4);
    cvt_f16_kernel<<<(nw4+255)/256, 256>>>((const float4*)(gwt + 2*DDIM*DDIM), (uint2*)(gwt16 + 2*DDIM*DDIM/2), nw4);

    const size_t NA = (size_t)BNUM*SLEN*DDIM;
    const int na4 = (int)(NA/4);
    cvt_f16_kernel<<<(na4+255)/256, 256>>>((const float4*)q, (uint2*)(gaf16 + 0*NA/2), na4);
    cvt_f16_kernel<<<(na4+255)/256, 256>>>((const float4*)k, (uint2*)(gaf16 + 1*NA/2), na4);
    cvt_f16_kernel<<<(na4+255)/256, 256>>>((const float4*)v, (uint2*)(gaf16 + 2*NA/2), na4);

    // Projections (fp16 HMMA, cp.async).
    const int proj_smem = 2 * 2 * 128 * PPD * 4;  // 40960
    cudaFuncSetAttribute(proj_mma_kernel,
        cudaFuncAttributeMaxDynamicSharedMemorySize, proj_smem);
    dim3 pgrid(DDIM/128, (BNUM*SLEN)/128, 3);
    proj_mma_kernel<<<pgrid, 256, proj_smem>>>(
        gaf16 + 0*NA/2, gaf16 + 1*NA/2, gaf16 + 2*NA/2,
        gwt16 + 0*DDIM*DDIM/2, gwt16 + 1*DDIM*DDIM/2, gwt16 + 2*DDIM*DDIM/2,
        bq, bk, bv,
        gq, gk, gv);

    // Attention pre-passes: Q/K split, V pack-transpose.
    const int nw = BNUM*HNUM*SLEN*DKQ/2;
    split_qk_kernel<<<dim3((nw+255)/256, 2), 256>>>(
        (const float2*)gq, (const float2*)gk, gqh, gql, gkh, gkl, nw);
    vt_kernel<<<dim3(BNUM*HNUM, SLEN/64), 128>>>(gv, gvt);

    // Attention.
    const int attn_smem = (18432 + 2304) * 4;     // 82944
    cudaFuncSetAttribute(attn_mma_kernel,
        cudaFuncAttributeMaxDynamicSharedMemorySize, attn_smem);
    attn_mma_kernel<<<dim3(BNUM*HNUM, SLEN/64), 128, attn_smem>>>(
        gqh, gql, gkh, gkl, gvt, out);
}